// round 1
// baseline (speedup 1.0000x reference)
#include <cuda_runtime.h>
#include <math.h>

#define NPIX 262144
#define NCH  256
#define NK   24     // n_knots + degree + 1 = 20 + 3 + 1
#define ND   22     // NK - 2 rows of the 2nd-difference operator
#define PPI  4      // pixels per block iteration

#define C1F  1.191042e-08f
#define C2F  1.4387769f

// ---------------- scratch (no allocations allowed) ----------------
__device__ double g_res;
__device__ double g_ss;
__device__ double g_bv;

__device__ float4 g_w[NCH];     // 4 nonzero spline weights per channel
__device__ int    g_k0[NCH];    // start index of nonzero support
__device__ float  g_c1v3[NCH];  // C1 * v^3
__device__ float  g_c2v[NCH];   // C2 * v
__device__ float  g_sg[NCH];    // s_ground
__device__ float  g_dsg[NCH];   // s_sky - s_ground

// ---------------- prep: zero accumulators + pack tables ----------------
__global__ void prep_kernel(const float* __restrict__ phi,
                            const float* __restrict__ s_sky,
                            const float* __restrict__ s_ground,
                            const float* __restrict__ wn)
{
    int c = threadIdx.x;
    if (c == 0) { g_res = 0.0; g_ss = 0.0; g_bv = 0.0; }
    if (c < NCH) {
        const float* row = phi + c * NK;
        int k0 = 0;
        #pragma unroll
        for (int k = 0; k < NK; ++k) {
            if (row[k] != 0.0f) { k0 = k; break; }
        }
        if (k0 > NK - 4) k0 = NK - 4;   // clamp so k0..k0+3 in range (extras are exact 0)
        g_k0[c] = k0;
        g_w[c]  = make_float4(row[k0], row[k0 + 1], row[k0 + 2], row[k0 + 3]);
        float v = wn[c];
        g_c1v3[c] = C1F * v * v * v;
        g_c2v[c]  = C2F * v;
        float sg = s_ground[c];
        g_sg[c]  = sg;
        g_dsg[c] = s_sky[c] - sg;
    }
}

// ---------------- main: fused model + residual + smoothness + bounds ----------------
__global__ void __launch_bounds__(256, 8)
main_kernel(const float* __restrict__ s_obs,
            const float* __restrict__ temperature,
            const float* __restrict__ beta,
            const float* __restrict__ view_factor,
            float* __restrict__ s_model)
{
    __shared__ float sb[PPI][NK];     // beta tiles for PPI pixels
    __shared__ float sInvT[PPI];
    __shared__ float sVf[PPI];
    __shared__ float wr[8], wb[8], ws[8];

    const int t    = threadIdx.x;     // t == channel index
    const int wid  = t >> 5;
    const int lane = t & 31;

    // per-channel constants -> registers (channel fixed per thread)
    const int    k0c  = g_k0[t];
    const float4 wc   = g_w[t];
    const float  c1   = g_c1v3[t];
    const float  c2   = g_c2v[t];
    const float  sgc  = g_sg[t];
    const float  dsgc = g_dsg[t];

    float rs  = 0.0f;   // sum of squared residuals
    float bvs = 0.0f;   // bound violations
    float sss = 0.0f;   // smoothness sum-of-squares

    for (int base = blockIdx.x * PPI; base < NPIX; base += gridDim.x * PPI) {
        // stage beta (coalesced: addr = base*NK + t), T, vf
        if (t < PPI * NK) {
            sb[t / NK][t % NK] = beta[base * NK + t];
        }
        if (t >= 128 && t < 128 + PPI)
            sInvT[t - 128] = __frcp_rn(temperature[base + (t - 128)]);
        if (t >= 160 && t < 160 + PPI)
            sVf[t - 160] = view_factor[base + (t - 160)];
        __syncthreads();

        // smoothness from the staged beta tile (threads 0..87)
        if (t < PPI * ND) {
            int p = t / ND, j = t % ND;
            float d = sb[p][j] - 2.0f * sb[p][j + 1] + sb[p][j + 2];
            sss = fmaf(d, d, sss);
        }

        // prefetch s_obs for MLP
        float so[PPI];
        #pragma unroll
        for (int p = 0; p < PPI; ++p)
            so[p] = s_obs[(size_t)(base + p) * NCH + t];

        #pragma unroll
        for (int p = 0; p < PPI; ++p) {
            const float* b = sb[p];
            float e = wc.x * b[k0c];
            e = fmaf(wc.y, b[k0c + 1], e);
            e = fmaf(wc.z, b[k0c + 2], e);
            e = fmaf(wc.w, b[k0c + 3], e);

            float arg = c2 * sInvT[p];
            float pl  = c1 * __frcp_rn(__expf(arg) - 1.0f);  // Planck (no cancellation: arg >= 2.3)
            float xa  = fmaf(sVf[p], dsgc, sgc);             // ambient
            float sm  = fmaf(e, pl - xa, xa);

            s_model[(size_t)(base + p) * NCH + t] = sm;

            float r = so[p] - sm;
            rs = fmaf(r, r, rs);
            bvs += fmaxf(0.01f - e, 0.0f) + fmaxf(e - 0.99f, 0.0f);
        }
        __syncthreads();   // protect sb before next overwrite
    }

    // block reduction -> one double atomic per quantity per block
    const unsigned m = 0xffffffffu;
    #pragma unroll
    for (int o = 16; o > 0; o >>= 1) {
        rs  += __shfl_down_sync(m, rs,  o);
        bvs += __shfl_down_sync(m, bvs, o);
        sss += __shfl_down_sync(m, sss, o);
    }
    if (lane == 0) { wr[wid] = rs; wb[wid] = bvs; ws[wid] = sss; }
    __syncthreads();
    if (wid == 0) {
        float a = (lane < 8) ? wr[lane] : 0.0f;
        float b = (lane < 8) ? wb[lane] : 0.0f;
        float c = (lane < 8) ? ws[lane] : 0.0f;
        #pragma unroll
        for (int o = 4; o > 0; o >>= 1) {
            a += __shfl_down_sync(m, a, o);
            b += __shfl_down_sync(m, b, o);
            c += __shfl_down_sync(m, c, o);
        }
        if (lane == 0) {
            atomicAdd(&g_res, (double)a);
            atomicAdd(&g_bv,  (double)b);
            atomicAdd(&g_ss,  (double)c);
        }
    }
}

// ---------------- finalize: write scalar total ----------------
__global__ void finalize_kernel(float* __restrict__ out_total)
{
    const double n = (double)NPIX;
    // total = mean(res) + (REG_LAMBDA/2)*mean(ss) + MU*mean(bv)
    out_total[0] = (float)(g_res / n + 0.5 * g_ss / n + 10.0 * g_bv / n);
}

// ---------------- launch ----------------
extern "C" void kernel_launch(void* const* d_in, const int* in_sizes, int n_in,
                              void* d_out, int out_size)
{
    const float* s_obs       = (const float*)d_in[0];
    const float* temperature = (const float*)d_in[1];
    const float* beta        = (const float*)d_in[2];
    const float* view_factor = (const float*)d_in[3];
    const float* s_sky       = (const float*)d_in[4];
    const float* s_ground    = (const float*)d_in[5];
    const float* phi         = (const float*)d_in[6];
    // d_in[7] = d_beta (structure known analytically), d_in[8] = wavenumber_grid
    const float* wn          = (const float*)d_in[8];

    float* out = (float*)d_out;
    // output = concat(total[1], s_model[NPIX*NCH]) flattened
    int off = out_size - NPIX * NCH;          // expected 1
    float* smodel = out + (off > 0 ? off : 0);

    prep_kernel<<<1, 256>>>(phi, s_sky, s_ground, wn);
    main_kernel<<<2048, 256>>>(s_obs, temperature, beta, view_factor, smodel);
    if (off > 0) finalize_kernel<<<1, 1>>>(out);
}

// round 2
// speedup vs baseline: 1.3257x; 1.3257x over previous
#include <cuda_runtime.h>
#include <math.h>

#define NPIX 262144
#define NCH  256
#define NK   24          // n_knots + degree + 1
#define ND   22          // NK - 2 second-difference rows
#define PPI  8           // pixels per tile
#define NTILES (NPIX / PPI)
#define GRID 592         // 148 SMs * 4 resident blocks

#define C1F  1.191042e-08f
#define C2F  1.4387769f

// ---------------- persistent device scratch (no allocations) ----------------
__device__ double   g_res;
__device__ double   g_ss;
__device__ double   g_bv;
__device__ unsigned g_count;

__global__ void __launch_bounds__(256, 4)
fused_kernel(const float* __restrict__ s_obs,
             const float* __restrict__ temperature,
             const float* __restrict__ beta,
             const float* __restrict__ view_factor,
             const float* __restrict__ s_sky,
             const float* __restrict__ s_ground,
             const float* __restrict__ phi,
             const float* __restrict__ wn,
             float* __restrict__ s_model,
             float* __restrict__ out_total,
             int write_total)
{
    __shared__ float sb[2][PPI * NK];   // beta tiles (double buffered)
    __shared__ float sT[2][PPI];        // 1/T
    __shared__ float sV[2][PPI];        // view factor
    __shared__ float wred[3][8];

    const int t    = threadIdx.x;       // t == channel
    const int wid  = t >> 5;
    const int lane = t & 31;

    // ---- per-channel constants (one-time, L2-resident after first wave) ----
    const float* row = phi + t * NK;
    int k0 = 0;
    #pragma unroll
    for (int k = 0; k < NK; ++k) {
        if (row[k] != 0.0f) { k0 = k; break; }
    }
    if (k0 > NK - 4) k0 = NK - 4;
    const float w0 = row[k0],     w1 = row[k0 + 1];
    const float w2 = row[k0 + 2], w3 = row[k0 + 3];
    const float v   = wn[t];
    const float c1  = C1F * v * v * v;
    const float c2  = C2F * v;
    const float sg  = s_ground[t];
    const float dsg = s_sky[t] - sg;

    float rs  = 0.0f;   // residual sum of squares
    float bvs = 0.0f;   // bound violation
    float sss = 0.0f;   // smoothness sum of squares

    // staging helper: threads 0..191 beta, 192..199 T, 200..207 vf
    auto stage = [&](int buf, int tile) {
        const int base = tile * PPI;
        if (t < PPI * NK) {
            sb[buf][t] = beta[base * NK + t];
        } else if (t < PPI * NK + PPI) {
            sT[buf][t - PPI * NK] = __frcp_rn(temperature[base + (t - PPI * NK)]);
        } else if (t < PPI * NK + 2 * PPI) {
            sV[buf][t - (PPI * NK + PPI)] = view_factor[base + (t - (PPI * NK + PPI))];
        }
    };

    int tile = blockIdx.x;
    stage(0, tile);                 // GRID=592 < NTILES, always valid
    __syncthreads();

    int buf = 0;
    for (; tile < NTILES; tile += GRID) {
        const int nxt = tile + GRID;
        if (nxt < NTILES) stage(buf ^ 1, nxt);   // overlap next tile's loads

        const int base = tile * PPI;

        // smoothness from the staged beta tile (threads 0..175)
        if (t < PPI * ND) {
            const int p = t / ND, j = t - p * ND;
            const float* b = &sb[buf][p * NK];
            const float d = b[j] - 2.0f * b[j + 1] + b[j + 2];
            sss = fmaf(d, d, sss);
        }

        // prefetch s_obs (streaming)
        float so[PPI];
        #pragma unroll
        for (int p = 0; p < PPI; ++p)
            so[p] = __ldcs(&s_obs[(size_t)(base + p) * NCH + t]);

        #pragma unroll
        for (int p = 0; p < PPI; ++p) {
            const float* b = &sb[buf][p * NK];
            float e = w0 * b[k0];
            e = fmaf(w1, b[k0 + 1], e);
            e = fmaf(w2, b[k0 + 2], e);
            e = fmaf(w3, b[k0 + 3], e);

            const float arg = c2 * sT[buf][p];
            const float pl  = __fdividef(c1, __expf(arg) - 1.0f); // arg>=2.3, no cancellation
            const float xa  = fmaf(sV[buf][p], dsg, sg);
            const float sm  = fmaf(e, pl - xa, xa);

            __stcs(&s_model[(size_t)(base + p) * NCH + t], sm);

            const float r = so[p] - sm;
            rs  = fmaf(r, r, rs);
            bvs += fmaxf(0.01f - e, 0.0f) + fmaxf(e - 0.99f, 0.0f);
        }

        __syncthreads();    // buf reads done; buf^1 writes done
        buf ^= 1;
    }

    // ---- block reduction ----
    const unsigned m = 0xffffffffu;
    #pragma unroll
    for (int o = 16; o > 0; o >>= 1) {
        rs  += __shfl_down_sync(m, rs,  o);
        bvs += __shfl_down_sync(m, bvs, o);
        sss += __shfl_down_sync(m, sss, o);
    }
    if (lane == 0) { wred[0][wid] = rs; wred[1][wid] = bvs; wred[2][wid] = sss; }
    __syncthreads();

    if (t == 0) {
        double a = 0.0, b = 0.0, c = 0.0;
        #pragma unroll
        for (int i = 0; i < 8; ++i) {
            a += (double)wred[0][i];
            b += (double)wred[1][i];
            c += (double)wred[2][i];
        }
        atomicAdd(&g_res, a);
        atomicAdd(&g_bv,  b);
        atomicAdd(&g_ss,  c);
        __threadfence();
        const unsigned done = atomicAdd(&g_count, 1u);
        if (done == (unsigned)(GRID - 1)) {
            // last block: all adds are visible (threadfence + acquire via atomic)
            const double rr = atomicAdd(&g_res, 0.0);
            const double bb = atomicAdd(&g_bv,  0.0);
            const double cc = atomicAdd(&g_ss,  0.0);
            const double n  = (double)NPIX;
            if (write_total)
                out_total[0] = (float)(rr / n + 0.5 * cc / n + 10.0 * bb / n);
            // reset for next (deterministic) call / graph replay
            g_res = 0.0; g_bv = 0.0; g_ss = 0.0; g_count = 0u;
        }
    }
}

// ---------------- launch ----------------
extern "C" void kernel_launch(void* const* d_in, const int* in_sizes, int n_in,
                              void* d_out, int out_size)
{
    const float* s_obs       = (const float*)d_in[0];
    const float* temperature = (const float*)d_in[1];
    const float* beta        = (const float*)d_in[2];
    const float* view_factor = (const float*)d_in[3];
    const float* s_sky       = (const float*)d_in[4];
    const float* s_ground    = (const float*)d_in[5];
    const float* phi         = (const float*)d_in[6];
    // d_in[7] = d_beta (2nd-difference operator, applied analytically)
    const float* wn          = (const float*)d_in[8];

    float* out = (float*)d_out;
    const int off = out_size - NPIX * NCH;   // expected 1 (total scalar first)
    float* smodel = out + (off > 0 ? off : 0);

    fused_kernel<<<GRID, 256>>>(s_obs, temperature, beta, view_factor,
                                s_sky, s_ground, phi, wn,
                                smodel, out, off > 0 ? 1 : 0);
}